// round 2
// baseline (speedup 1.0000x reference)
#include <cuda_runtime.h>
#include <math.h>

#define SEQ   4096
#define BATCH 4
#define DIMN  1024
#define NH    16
#define DH    64
#define NL    32
#define WW    8
#define EE    4
#define BAND  16
#define MROWS (BATCH*SEQ)
#define NCH   8
#define CHUNK (SEQ/NCH)

// ---------------- scratch (static device allocations, allowed) ----------------
__device__ float g_Q [(size_t)BATCH*SEQ*DIMN];
__device__ float g_K [(size_t)BATCH*SEQ*DIMN];
__device__ float g_V [(size_t)BATCH*SEQ*DIMN];
__device__ float g_Ds[(size_t)BATCH*SEQ*NH*NL];
__device__ float g_C [(size_t)BATCH*SEQ*DIMN];
__device__ float g_Kc[(size_t)BATCH*NL*DIMN];
__device__ float g_Vc[(size_t)BATCH*NL*DIMN];
__device__ float g_pK[(size_t)BATCH*NH*NCH*NL*DH];
__device__ float g_pV[(size_t)BATCH*NH*NCH*NL*DH];

// ---------------- block reductions (256 threads) ----------------
__device__ __forceinline__ float blk_sum256(float v, float* sh) {
    int t = threadIdx.x;
    #pragma unroll
    for (int o = 16; o; o >>= 1) v += __shfl_xor_sync(0xffffffffu, v, o);
    if ((t & 31) == 0) sh[t >> 5] = v;
    __syncthreads();
    if (t < 32) {
        float x = (t < 8) ? sh[t] : 0.f;
        #pragma unroll
        for (int o = 4; o; o >>= 1) x += __shfl_xor_sync(0xffffffffu, x, o);
        if (t == 0) sh[0] = x;
    }
    __syncthreads();
    float r = sh[0];
    __syncthreads();
    return r;
}

__device__ __forceinline__ float blk_max256(float v, float* sh) {
    int t = threadIdx.x;
    #pragma unroll
    for (int o = 16; o; o >>= 1) v = fmaxf(v, __shfl_xor_sync(0xffffffffu, v, o));
    if ((t & 31) == 0) sh[t >> 5] = v;
    __syncthreads();
    if (t < 32) {
        float x = (t < 8) ? sh[t] : -1e30f;
        #pragma unroll
        for (int o = 4; o; o >>= 1) x = fmaxf(x, __shfl_xor_sync(0xffffffffu, x, o));
        if (t == 0) sh[0] = x;
    }
    __syncthreads();
    float r = sh[0];
    __syncthreads();
    return r;
}

// ---------------- generic fp32 GEMM: out = alpha*(A@W + bias) ----------------
// A: (MROWS x 1024). remap_in: A row m=(b*S+s) lives at query[(s*B+b)*1024].
// remap_out: same permutation applied to output rows (final transpose).
__global__ void __launch_bounds__(256, 2)
gemm_kernel(const float* __restrict__ A, const float* __restrict__ Wt,
            const float* __restrict__ bias, float* __restrict__ out,
            int N, float alpha, int remap_in, int remap_out)
{
    __shared__ float As[16][128];
    __shared__ float Bs[16][128];
    const int t  = threadIdx.x;
    const int bx = blockIdx.x, by = blockIdx.y;
    const int tx = t & 15, ty = t >> 4;

    const int ar0 = t >> 2;
    const int ar1 = ar0 + 64;
    const int akq = (t & 3) << 2;
    const int m0  = by * 128 + ar0;
    const int m1  = by * 128 + ar1;
    const size_t arow0 = remap_in ? ((size_t)(m0 & (SEQ-1)) * BATCH + (m0 >> 12)) : (size_t)m0;
    const size_t arow1 = remap_in ? ((size_t)(m1 & (SEQ-1)) * BATCH + (m1 >> 12)) : (size_t)m1;
    const float* aptr0 = A + arow0 * DIMN + akq;
    const float* aptr1 = A + arow1 * DIMN + akq;

    const int bkr = t >> 5;          // 0..7
    const int bnc = (t & 31) << 2;   // 0..124
    const float* bptr0 = Wt + (size_t)bkr * N + bx * 128 + bnc;
    const float* bptr1 = bptr0 + (size_t)8 * N;

    float acc[8][8];
    #pragma unroll
    for (int i = 0; i < 8; i++)
        #pragma unroll
        for (int j = 0; j < 8; j++) acc[i][j] = 0.f;

    for (int kt = 0; kt < DIMN / 16; kt++) {
        float4 va0 = *(const float4*)(aptr0 + kt * 16);
        float4 va1 = *(const float4*)(aptr1 + kt * 16);
        float4 vb0 = *(const float4*)(bptr0 + (size_t)kt * 16 * N);
        float4 vb1 = *(const float4*)(bptr1 + (size_t)kt * 16 * N);
        __syncthreads();
        As[akq+0][ar0] = va0.x; As[akq+1][ar0] = va0.y;
        As[akq+2][ar0] = va0.z; As[akq+3][ar0] = va0.w;
        As[akq+0][ar1] = va1.x; As[akq+1][ar1] = va1.y;
        As[akq+2][ar1] = va1.z; As[akq+3][ar1] = va1.w;
        *(float4*)&Bs[bkr  ][bnc] = vb0;
        *(float4*)&Bs[bkr+8][bnc] = vb1;
        __syncthreads();
        #pragma unroll
        for (int kk = 0; kk < 16; kk++) {
            float4 a0 = *(const float4*)&As[kk][ty*8];
            float4 a1 = *(const float4*)&As[kk][ty*8+4];
            float4 b0 = *(const float4*)&Bs[kk][tx*8];
            float4 b1 = *(const float4*)&Bs[kk][tx*8+4];
            float ra[8] = {a0.x,a0.y,a0.z,a0.w,a1.x,a1.y,a1.z,a1.w};
            float rb[8] = {b0.x,b0.y,b0.z,b0.w,b1.x,b1.y,b1.z,b1.w};
            #pragma unroll
            for (int i = 0; i < 8; i++)
                #pragma unroll
                for (int j = 0; j < 8; j++)
                    acc[i][j] = fmaf(ra[i], rb[j], acc[i][j]);
        }
    }

    float bvals[8];
    #pragma unroll
    for (int j = 0; j < 8; j++) bvals[j] = bias[bx*128 + tx*8 + j];
    #pragma unroll
    for (int i = 0; i < 8; i++) {
        int m = by*128 + ty*8 + i;
        size_t orow = remap_out ? ((size_t)(m & (SEQ-1)) * BATCH + (m >> 12)) : (size_t)m;
        float* po = out + orow * N + bx*128 + tx*8;
        float4 v0, v1;
        v0.x = alpha*(acc[i][0]+bvals[0]); v0.y = alpha*(acc[i][1]+bvals[1]);
        v0.z = alpha*(acc[i][2]+bvals[2]); v0.w = alpha*(acc[i][3]+bvals[3]);
        v1.x = alpha*(acc[i][4]+bvals[4]); v1.y = alpha*(acc[i][5]+bvals[5]);
        v1.z = alpha*(acc[i][6]+bvals[6]); v1.w = alpha*(acc[i][7]+bvals[7]);
        *(float4*)po     = v0;
        *(float4*)(po+4) = v1;
    }
}

// ---------------- layernorm over last dim (1024), in place ----------------
__global__ void __launch_bounds__(256)
ln_kernel(float* __restrict__ data, const float* __restrict__ gamma,
          const float* __restrict__ beta)
{
    __shared__ float sh[32];
    const size_t row = blockIdx.x;
    float* p = data + row * DIMN;
    const int t = threadIdx.x;
    float4 v = ((const float4*)p)[t];
    float s = v.x + v.y + v.z + v.w;
    float mean = blk_sum256(s, sh) * (1.f / DIMN);
    float4 dx = {v.x - mean, v.y - mean, v.z - mean, v.w - mean};
    float sq = dx.x*dx.x + dx.y*dx.y + dx.z*dx.z + dx.w*dx.w;
    float var = blk_sum256(sq, sh) * (1.f / DIMN);
    float rstd = rsqrtf(var + 1e-5f);
    float4 g4 = ((const float4*)gamma)[t];
    float4 b4 = ((const float4*)beta)[t];
    float4 o4;
    o4.x = dx.x * rstd * g4.x + b4.x;
    o4.y = dx.y * rstd * g4.y + b4.y;
    o4.z = dx.z * rstd * g4.z + b4.z;
    o4.w = dx.w * rstd * g4.w + b4.w;
    ((float4*)p)[t] = o4;
}

// ---------------- softmax over s axis of D (b, s, 512), per (b, col) ----------------
__global__ void __launch_bounds__(256)
dsoftmax_kernel(float* __restrict__ D)
{
    __shared__ float sh[32];
    const int b = blockIdx.x >> 9;
    const int c = blockIdx.x & 511;
    const int t = threadIdx.x;
    float v[16];
    float mx = -1e30f;
    #pragma unroll
    for (int i = 0; i < 16; i++) {
        int s = i * 256 + t;
        v[i] = D[((size_t)(b * SEQ + s)) * (NH*NL) + c];
        mx = fmaxf(mx, v[i]);
    }
    mx = blk_max256(mx, sh);
    float sum = 0.f;
    #pragma unroll
    for (int i = 0; i < 16; i++) { v[i] = expf(v[i] - mx); sum += v[i]; }
    sum = blk_sum256(sum, sh);
    float inv = 1.f / sum;
    #pragma unroll
    for (int i = 0; i < 16; i++) {
        int s = i * 256 + t;
        D[((size_t)(b * SEQ + s)) * (NH*NL) + c] = v[i] * inv;
    }
}

// ---------------- compression partials: Kc/Vc = hs @ K/V over an s-chunk ----------------
__global__ void __launch_bounds__(256)
compress_kernel(const float* __restrict__ D, const float* __restrict__ K,
                const float* __restrict__ V,
                float* __restrict__ partK, float* __restrict__ partV)
{
    const int bh = blockIdx.x;         // 0..63
    const int chunk = blockIdx.y;      // 0..NCH-1
    const int b = bh >> 4, h = bh & 15;
    const int t = threadIdx.x;
    const int d = t & 63;
    const int lbase = (t >> 6) * 8;

    __shared__ float sh_hs[8][33];
    __shared__ float sh_K[8][64];
    __shared__ float sh_V[8][64];

    float accK[8], accV[8];
    #pragma unroll
    for (int i = 0; i < 8; i++) { accK[i] = 0.f; accV[i] = 0.f; }

    const int s0c = chunk * CHUNK;
    for (int stage = 0; stage < CHUNK / 8; stage++) {
        const int sbase = s0c + stage * 8;
        {
            int si = t >> 5, l = t & 31;
            sh_hs[si][l] = D[((size_t)(b * SEQ + sbase + si)) * (NH*NL) + h * NL + l];
        }
        {
            int si = t >> 6;
            #pragma unroll
            for (int j = 0; j < 2; j++) {
                int sii = si + j * 4;
                size_t src = ((size_t)(b * SEQ + sbase + sii)) * DIMN + h * DH + d;
                sh_K[sii][d] = K[src];
                sh_V[sii][d] = V[src];
            }
        }
        __syncthreads();
        #pragma unroll
        for (int si = 0; si < 8; si++) {
            float kv = sh_K[si][d], vv = sh_V[si][d];
            #pragma unroll
            for (int li = 0; li < 8; li++) {
                float hsv = sh_hs[si][lbase + li];
                accK[li] = fmaf(hsv, kv, accK[li]);
                accV[li] = fmaf(hsv, vv, accV[li]);
            }
        }
        __syncthreads();
    }
    #pragma unroll
    for (int li = 0; li < 8; li++) {
        size_t idx = (((size_t)bh * NCH + chunk) * NL + lbase + li) * DH + d;
        partK[idx] = accK[li];
        partV[idx] = accV[li];
    }
}

// ---------------- reduce partials -> Kc/Vc laid out (b, l, h*64+d) ----------------
__global__ void __launch_bounds__(256)
reduce_kc(const float* __restrict__ partK, const float* __restrict__ partV,
          float* __restrict__ Kc, float* __restrict__ Vc)
{
    const int e = blockIdx.x * 256 + threadIdx.x;   // over B*L*H*DH = 131072
    const int d = e & 63;
    const int h = (e >> 6) & 15;
    const int l = (e >> 10) & 31;
    const int b = e >> 15;
    const int bh = b * NH + h;
    float sK = 0.f, sV = 0.f;
    #pragma unroll
    for (int c = 0; c < NCH; c++) {
        size_t idx = (((size_t)bh * NCH + c) * NL + l) * DH + d;
        sK += partK[idx];
        sV += partV[idx];
    }
    size_t o = ((size_t)(b * NL + l)) * DIMN + h * DH + d;
    Kc[o] = sK;
    Vc[o] = sV;
}

// ---------------- fused attention (compressed 32 keys + window 16 keys) ----------------
#define GPB 2
#define NQ  (GPB*WW)               // 16 queries per block
#define NWK ((GPB-1)*WW + BAND)    // 24 window rows

__global__ void __launch_bounds__(256)
attn_kernel(const float* __restrict__ Q, const float* __restrict__ K,
            const float* __restrict__ V, const float* __restrict__ Kc,
            const float* __restrict__ Vc, float* __restrict__ C)
{
    const int gblk = blockIdx.x;          // 0..255
    const int h = blockIdx.y;
    const int b = blockIdx.z;
    const int s0  = gblk * NQ;            // first query s
    const int wk0 = s0 - EE;              // first window key s (may be <0)

    __shared__ float sKc[NL][68];
    __shared__ float sVc[NL][68];
    __shared__ float sKw[NWK][68];
    __shared__ float sVw[NWK][68];
    __shared__ float sQ [NQ][68];
    __shared__ float sp [NQ][48];

    const int t = threadIdx.x;

    for (int i = t; i < NL * DH; i += 256) {
        int l = i >> 6, d = i & 63;
        size_t src = ((size_t)(b * NL + l)) * DIMN + h * DH + d;
        sKc[l][d] = Kc[src];
        sVc[l][d] = Vc[src];
    }
    for (int i = t; i < NQ * DH; i += 256) {
        int q = i >> 6, d = i & 63;
        sQ[q][d] = Q[((size_t)(b * SEQ + s0 + q)) * DIMN + h * DH + d];
    }
    for (int i = t; i < NWK * DH; i += 256) {
        int r = i >> 6, d = i & 63;
        int sk = wk0 + r;
        float kv = 0.f, vv = 0.f;
        if (sk >= 0 && sk < SEQ) {
            size_t src = ((size_t)(b * SEQ + sk)) * DIMN + h * DH + d;
            kv = K[src]; vv = V[src];
        }
        sKw[r][d] = kv;
        sVw[r][d] = vv;
    }
    __syncthreads();

    const int warp = t >> 5, lane = t & 31;
    #pragma unroll
    for (int qq = 0; qq < 2; qq++) {
        const int q = warp * 2 + qq;       // 0..15
        const int grp = q >> 3;            // group within block
        const int woff = grp * WW;         // window buffer row offset
        const float* qrow  = sQ[q];
        const float* krow0 = sKc[lane];
        const float* krow1 = sKw[woff + (lane & 15)];
        float sc0 = 0.f, sc1 = 0.f;
        #pragma unroll
        for (int dd = 0; dd < DH; dd += 4) {
            float4 qa = *(const float4*)(qrow + dd);
            float4 ka = *(const float4*)(krow0 + dd);
            float4 kb = *(const float4*)(krow1 + dd);
            sc0 += qa.x*ka.x + qa.y*ka.y + qa.z*ka.z + qa.w*ka.w;
            sc1 += qa.x*kb.x + qa.y*kb.y + qa.z*kb.z + qa.w*kb.w;
        }
        bool wvalid = (lane < 16);
        if (wvalid) {
            int sk = wk0 + woff + lane;
            if (sk < 0 || sk >= SEQ) wvalid = false;
        }
        float swin = wvalid ? sc1 : -1e30f;
        float m = fmaxf(sc0, swin);
        #pragma unroll
        for (int o = 16; o; o >>= 1) m = fmaxf(m, __shfl_xor_sync(0xffffffffu, m, o));
        float e0 = expf(sc0 - m);
        float e1 = wvalid ? expf(swin - m) : 0.f;
        float ssum = e0 + e1;
        #pragma unroll
        for (int o = 16; o; o >>= 1) ssum += __shfl_xor_sync(0xffffffffu, ssum, o);
        float inv = 1.f / ssum;
        sp[q][lane] = e0 * inv;
        if (lane < 16) sp[q][32 + lane] = e1 * inv;
    }
    __syncthreads();

    for (int i = t; i < NQ * DH; i += 256) {
        int q = i >> 6, d = i & 63;
        int woff = (q >> 3) * WW;
        float acc = 0.f;
        #pragma unroll
        for (int l = 0; l < NL; l++) acc = fmaf(sp[q][l], sVc[l][d], acc);
        #pragma unroll
        for (int j = 0; j < BAND; j++) acc = fmaf(sp[q][32 + j], sVw[woff + j][d], acc);
        C[((size_t)(b * SEQ + s0 + q)) * DIMN + h * DH + d] = acc;
    }
}

// ---------------- launch ----------------
extern "C" void kernel_launch(void* const* d_in, const int* in_sizes, int n_in,
                              void* d_out, int out_size)
{
    const float* query = (const float*)d_in[0];
    const float* Wq  = (const float*)d_in[1];
    const float* bq  = (const float*)d_in[2];
    const float* Wk  = (const float*)d_in[3];
    const float* bk  = (const float*)d_in[4];
    const float* Wv  = (const float*)d_in[5];
    const float* bv  = (const float*)d_in[6];
    const float* Wo  = (const float*)d_in[7];
    const float* bo  = (const float*)d_in[8];
    const float* g_l = (const float*)d_in[9];
    const float* b_l = (const float*)d_in[10];
    const float* g_s = (const float*)d_in[11];
    const float* b_s = (const float*)d_in[12];
    const float* Wd  = (const float*)d_in[13];
    const float* bd  = (const float*)d_in[14];
    float* out = (float*)d_out;

    float *Qb, *Kb, *Vb, *Db, *Cb, *Kcb, *Vcb, *pK, *pV;
    cudaGetSymbolAddress((void**)&Qb,  g_Q);
    cudaGetSymbolAddress((void**)&Kb,  g_K);
    cudaGetSymbolAddress((void**)&Vb,  g_V);
    cudaGetSymbolAddress((void**)&Db,  g_Ds);
    cudaGetSymbolAddress((void**)&Cb,  g_C);
    cudaGetSymbolAddress((void**)&Kcb, g_Kc);
    cudaGetSymbolAddress((void**)&Vcb, g_Vc);
    cudaGetSymbolAddress((void**)&pK,  g_pK);
    cudaGetSymbolAddress((void**)&pV,  g_pV);

    // Projections: Q (scaled by 1/sqrt(DH) AFTER bias, per reference), K, V, D
    gemm_kernel<<<dim3(8, 128), 256>>>(query, Wq, bq, Qb, 1024, 0.125f, 1, 0);
    gemm_kernel<<<dim3(8, 128), 256>>>(query, Wk, bk, Kb, 1024, 1.0f,   1, 0);
    gemm_kernel<<<dim3(8, 128), 256>>>(query, Wv, bv, Vb, 1024, 1.0f,   1, 0);
    gemm_kernel<<<dim3(4, 128), 256>>>(query, Wd, bd, Db,  512, 1.0f,   1, 0);

    // LayerNorm on K, V (pre-split, over DIM)
    ln_kernel<<<MROWS, 256>>>(Kb, g_l, b_l);
    ln_kernel<<<MROWS, 256>>>(Vb, g_l, b_l);

    // head_scores softmax over sequence axis
    dsoftmax_kernel<<<BATCH * NH * NL, 256>>>(Db);

    // Compression: Kc/Vc = hs @ K/V  (partials + deterministic reduce)
    compress_kernel<<<dim3(BATCH * NH, NCH), 256>>>(Db, Kb, Vb, pK, pV);
    reduce_kc<<<(BATCH * NL * DIMN) / 256, 256>>>(pK, pV, Kcb, Vcb);

    // LayerNorm on compressed keys/values (over DIM, g_s/b_s)
    ln_kernel<<<BATCH * NL, 256>>>(Kcb, g_s, b_s);
    ln_kernel<<<BATCH * NL, 256>>>(Vcb, g_s, b_s);

    // Fused long-short attention -> C (b, s, DIM)
    attn_kernel<<<dim3(SEQ / NQ, NH, BATCH), 256>>>(Qb, Kb, Vb, Kcb, Vcb, Cb);

    // Output projection with transposed write to (s, b, DIM)
    gemm_kernel<<<dim3(8, 128), 256>>>(Cb, Wo, bo, out, 1024, 1.0f, 0, 1);
}

// round 5
// speedup vs baseline: 2.5976x; 2.5976x over previous
#include <cuda_runtime.h>
#include <math.h>
#include <stdint.h>

#define SEQ   4096
#define BATCH 4
#define DIMN  1024
#define NH    16
#define DH    64
#define NL    32
#define WW    8
#define EE    4
#define BAND  16
#define MROWS (BATCH*SEQ)
#define NCH   8
#define CHUNK (SEQ/NCH)

// ---------------- scratch ----------------
__device__ float g_Q [(size_t)BATCH*SEQ*DIMN];
__device__ float g_K [(size_t)BATCH*SEQ*DIMN];
__device__ float g_V [(size_t)BATCH*SEQ*DIMN];
__device__ float g_Ds[(size_t)BATCH*SEQ*NH*NL];   // transposed: (b, c=512, s=4096)
__device__ float g_C [(size_t)BATCH*SEQ*DIMN];
__device__ float g_Kc[(size_t)BATCH*NL*DIMN];
__device__ float g_Vc[(size_t)BATCH*NL*DIMN];
__device__ float g_pK[(size_t)BATCH*NH*NCH*NL*DH];
__device__ float g_pV[(size_t)BATCH*NH*NCH*NL*DH];

// ---------------- helpers ----------------
__device__ __forceinline__ uint32_t f2tf32(float x) {
    uint32_t u;
    asm("cvt.rna.tf32.f32 %0, %1;" : "=r"(u) : "f"(x));
    return u;
}

__device__ __forceinline__ void mma_tf32(float* c, const uint32_t* a, const uint32_t* b) {
    asm volatile(
        "mma.sync.aligned.m16n8k8.row.col.f32.tf32.tf32.f32 "
        "{%0,%1,%2,%3}, {%4,%5,%6,%7}, {%8,%9}, {%0,%1,%2,%3};"
        : "+f"(c[0]), "+f"(c[1]), "+f"(c[2]), "+f"(c[3])
        : "r"(a[0]), "r"(a[1]), "r"(a[2]), "r"(a[3]), "r"(b[0]), "r"(b[1]));
}

__device__ __forceinline__ void cp_async16(uint32_t dst, const void* src) {
    asm volatile("cp.async.cg.shared.global [%0], [%1], 16;" :: "r"(dst), "l"(src));
}
#define CP_COMMIT() asm volatile("cp.async.commit_group;")
#define CP_WAIT1()  asm volatile("cp.async.wait_group 1;")
#define CP_WAIT0()  asm volatile("cp.async.wait_group 0;")

__device__ __forceinline__ float blk_sum256(float v, float* sh) {
    int t = threadIdx.x;
    #pragma unroll
    for (int o = 16; o; o >>= 1) v += __shfl_xor_sync(0xffffffffu, v, o);
    if ((t & 31) == 0) sh[t >> 5] = v;
    __syncthreads();
    if (t < 32) {
        float x = (t < 8) ? sh[t] : 0.f;
        #pragma unroll
        for (int o = 4; o; o >>= 1) x += __shfl_xor_sync(0xffffffffu, x, o);
        if (t == 0) sh[0] = x;
    }
    __syncthreads();
    float r = sh[0];
    __syncthreads();
    return r;
}

__device__ __forceinline__ float blk_max256(float v, float* sh) {
    int t = threadIdx.x;
    #pragma unroll
    for (int o = 16; o; o >>= 1) v = fmaxf(v, __shfl_xor_sync(0xffffffffu, v, o));
    if ((t & 31) == 0) sh[t >> 5] = v;
    __syncthreads();
    if (t < 32) {
        float x = (t < 8) ? sh[t] : -1e30f;
        #pragma unroll
        for (int o = 4; o; o >>= 1) x = fmaxf(x, __shfl_xor_sync(0xffffffffu, x, o));
        if (t == 0) sh[0] = x;
    }
    __syncthreads();
    float r = sh[0];
    __syncthreads();
    return r;
}

// ---------------- tf32 tensor-core GEMM ----------------
// out = alpha*(A@W + bias). A is (16384 x 1024). K fixed = 1024.
// remap_in:  A row m=(b*S+s) lives at A[(s*B+b)*1024]
// remap_out: 0 = direct (m,N); 1 = transpose rows to (s*B+b); 2 = D-transpose (b, col, s)
#define BM 128
#define BN 128
#define BKK 32
#define ASTRIDE 36
#define BSTRIDE 136
#define A_FLOATS (BM*ASTRIDE)                 // 4608
#define STAGE_FLOATS (A_FLOATS + BKK*BSTRIDE) // 4608 + 4352 = 8960
#define STAGE_BYTES (STAGE_FLOATS*4)          // 35840
#define GEMM_SMEM (2*STAGE_BYTES)             // 71680

__global__ void __launch_bounds__(256, 2)
gemm_tf32(const float* __restrict__ A, const float* __restrict__ Wt,
          const float* __restrict__ bias, float* __restrict__ out,
          int N, float alpha, int remap_in, int remap_out)
{
    extern __shared__ float smem[];
    const uint32_t smem_u32 = (uint32_t)__cvta_generic_to_shared(smem);
    const int t  = threadIdx.x;
    const int bx = blockIdx.x, by = blockIdx.y;
    const int lane = t & 31;
    const int warp = t >> 5;
    const int wm = (warp & 1) * 64;   // 2 warps in M
    const int wn = (warp >> 1) * 32;  // 4 warps in N

    // ---- load-phase thread mapping ----
    const int lar = t >> 3;          // A row lane 0..31
    const int lac = (t & 7) * 4;     // A col (floats)
    const float* aSrc[4];
    uint32_t aOff[4];
    #pragma unroll
    for (int i = 0; i < 4; i++) {
        int m = by * BM + lar + i * 32;
        size_t arow = remap_in ? ((size_t)(m & (SEQ-1)) * BATCH + (m >> 12)) : (size_t)m;
        aSrc[i] = A + arow * DIMN + lac;
        aOff[i] = (uint32_t)(((lar + i * 32) * ASTRIDE + lac) * 4);
    }
    const int lbr = t >> 5;          // B k-row 0..7
    const int lbc = (t & 31) * 4;    // B col (floats)
    const float* bSrc = Wt + (size_t)lbr * N + bx * BN + lbc;
    uint32_t bOff[4];
    #pragma unroll
    for (int i = 0; i < 4; i++)
        bOff[i] = (uint32_t)(A_FLOATS * 4 + ((lbr + i * 8) * BSTRIDE + lbc) * 4);

    float acc[4][4][4];
    #pragma unroll
    for (int mi = 0; mi < 4; mi++)
        #pragma unroll
        for (int ni = 0; ni < 4; ni++)
            #pragma unroll
            for (int r = 0; r < 4; r++) acc[mi][ni][r] = 0.f;

    // ---- prologue: stages 0, 1 ----
    #pragma unroll
    for (int s = 0; s < 2; s++) {
        uint32_t sb = smem_u32 + s * STAGE_BYTES;
        int k0 = s * BKK;
        #pragma unroll
        for (int i = 0; i < 4; i++) cp_async16(sb + aOff[i], aSrc[i] + k0);
        #pragma unroll
        for (int i = 0; i < 4; i++) cp_async16(sb + bOff[i], bSrc + (size_t)(k0 + i * 8) * N);
        CP_COMMIT();
    }

    const int NKT = DIMN / BKK;   // 32
    #pragma unroll 1
    for (int kt = 0; kt < NKT; kt++) {
        if (kt < NKT - 1) { CP_WAIT1(); } else { CP_WAIT0(); }
        __syncthreads();

        const float* As = smem + (kt & 1) * STAGE_FLOATS;
        const float* Bs = As + A_FLOATS;

        #pragma unroll
        for (int ks = 0; ks < 4; ks++) {
            const int kk = ks * 8;
            uint32_t af[4][4], bf[4][2];
            #pragma unroll
            for (int mi = 0; mi < 4; mi++) {
                const float* ar = As + (wm + mi * 16 + (lane >> 2)) * ASTRIDE + kk + (lane & 3);
                af[mi][0] = f2tf32(ar[0]);
                af[mi][1] = f2tf32(ar[8 * ASTRIDE]);
                af[mi][2] = f2tf32(ar[4]);
                af[mi][3] = f2tf32(ar[8 * ASTRIDE + 4]);
            }
            #pragma unroll
            for (int ni = 0; ni < 4; ni++) {
                const float* br = Bs + (kk + (lane & 3)) * BSTRIDE + wn + ni * 8 + (lane >> 2);
                bf[ni][0] = f2tf32(br[0]);
                bf[ni][1] = f2tf32(br[4 * BSTRIDE]);
            }
            #pragma unroll
            for (int mi = 0; mi < 4; mi++)
                #pragma unroll
                for (int ni = 0; ni < 4; ni++)
                    mma_tf32(acc[mi][ni], af[mi], bf[ni]);
        }

        __syncthreads();
        if (kt < NKT - 2) {
            uint32_t sb = smem_u32 + (kt & 1) * STAGE_BYTES;
            int k0 = (kt + 2) * BKK;
            #pragma unroll
            for (int i = 0; i < 4; i++) cp_async16(sb + aOff[i], aSrc[i] + k0);
            #pragma unroll
            for (int i = 0; i < 4; i++) cp_async16(sb + bOff[i], bSrc + (size_t)(k0 + i * 8) * N);
            CP_COMMIT();
        }
    }

    // ---- epilogue ----
    #pragma unroll
    for (int ni = 0; ni < 4; ni++) {
        int col = bx * BN + wn + ni * 8 + 2 * (lane & 3);
        float bv0 = bias[col], bv1 = bias[col + 1];
        #pragma unroll
        for (int mi = 0; mi < 4; mi++) {
            const float* a = acc[mi][ni];
            int m0 = by * BM + wm + mi * 16 + (lane >> 2);
            int m1 = m0 + 8;
            float o00 = alpha * (a[0] + bv0), o01 = alpha * (a[1] + bv1);
            float o10 = alpha * (a[2] + bv0), o11 = alpha * (a[3] + bv1);
            if (remap_out == 2) {
                // (b, col, s) transposed store
                out[((size_t)((m0 >> 12) * (NH*NL) + col    )) * SEQ + (m0 & (SEQ-1))] = o00;
                out[((size_t)((m0 >> 12) * (NH*NL) + col + 1)) * SEQ + (m0 & (SEQ-1))] = o01;
                out[((size_t)((m1 >> 12) * (NH*NL) + col    )) * SEQ + (m1 & (SEQ-1))] = o10;
                out[((size_t)((m1 >> 12) * (NH*NL) + col + 1)) * SEQ + (m1 & (SEQ-1))] = o11;
            } else {
                size_t r0 = remap_out ? ((size_t)(m0 & (SEQ-1)) * BATCH + (m0 >> 12)) : (size_t)m0;
                size_t r1 = remap_out ? ((size_t)(m1 & (SEQ-1)) * BATCH + (m1 >> 12)) : (size_t)m1;
                float2 v0 = make_float2(o00, o01);
                float2 v1 = make_float2(o10, o11);
                *(float2*)(out + r0 * N + col) = v0;
                *(float2*)(out + r1 * N + col) = v1;
            }
        }
    }
}

// ---------------- layernorm over last dim (1024), in place ----------------
__global__ void __launch_bounds__(256)
ln_kernel(float* __restrict__ data, const float* __restrict__ gamma,
          const float* __restrict__ beta)
{
    __shared__ float sh[32];
    const size_t row = blockIdx.x;
    float* p = data + row * DIMN;
    const int t = threadIdx.x;
    float4 v = ((const float4*)p)[t];
    float s = v.x + v.y + v.z + v.w;
    float mean = blk_sum256(s, sh) * (1.f / DIMN);
    float4 dx = {v.x - mean, v.y - mean, v.z - mean, v.w - mean};
    float sq = dx.x*dx.x + dx.y*dx.y + dx.z*dx.z + dx.w*dx.w;
    float var = blk_sum256(sq, sh) * (1.f / DIMN);
    float rstd = rsqrtf(var + 1e-5f);
    float4 g4 = ((const float4*)gamma)[t];
    float4 b4 = ((const float4*)beta)[t];
    float4 o4;
    o4.x = dx.x * rstd * g4.x + b4.x;
    o4.y = dx.y * rstd * g4.y + b4.y;
    o4.z = dx.z * rstd * g4.z + b4.z;
    o4.w = dx.w * rstd * g4.w + b4.w;
    ((float4*)p)[t] = o4;
}

// ---------------- softmax over contiguous rows of Dt (b*512 rows of 4096) ----------------
__global__ void __launch_bounds__(256)
dsoftmax_kernel(float* __restrict__ Dt)
{
    __shared__ float sh[32];
    float* p = Dt + (size_t)blockIdx.x * SEQ;
    const int t = threadIdx.x;
    float4 v[4];
    float mx = -1e30f;
    #pragma unroll
    for (int i = 0; i < 4; i++) {
        v[i] = ((const float4*)p)[t + i * 256];
        mx = fmaxf(mx, fmaxf(fmaxf(v[i].x, v[i].y), fmaxf(v[i].z, v[i].w)));
    }
    mx = blk_max256(mx, sh);
    float sum = 0.f;
    #pragma unroll
    for (int i = 0; i < 4; i++) {
        v[i].x = expf(v[i].x - mx); v[i].y = expf(v[i].y - mx);
        v[i].z = expf(v[i].z - mx); v[i].w = expf(v[i].w - mx);
        sum += v[i].x + v[i].y + v[i].z + v[i].w;
    }
    sum = blk_sum256(sum, sh);
    float inv = 1.f / sum;
    #pragma unroll
    for (int i = 0; i < 4; i++) {
        v[i].x *= inv; v[i].y *= inv; v[i].z *= inv; v[i].w *= inv;
        ((float4*)p)[t + i * 256] = v[i];
    }
}

// ---------------- compression partials: Kc/Vc = hs @ K/V over an s-chunk ----------------
// Dt layout (b, c=h*32+l, s)
__global__ void __launch_bounds__(256)
compress_kernel(const float* __restrict__ Dt, const float* __restrict__ K,
                const float* __restrict__ V,
                float* __restrict__ partK, float* __restrict__ partV)
{
    const int bh = blockIdx.x;         // 0..63
    const int chunk = blockIdx.y;      // 0..NCH-1
    const int b = bh >> 4, h = bh & 15;
    const int t = threadIdx.x;
    const int d = t & 63;
    const int lbase = (t >> 6) * 8;

    __shared__ float sh_hs[NL][36];    // [l][si]
    __shared__ float sh_K[32][64];
    __shared__ float sh_V[32][64];

    float accK[8], accV[8];
    #pragma unroll
    for (int i = 0; i < 8; i++) { accK[i] = 0.f; accV[i] = 0.f; }

    const int lrow = t >> 3;           // 0..31
    const int s4   = (t & 7) * 4;
    const float* dtrow = Dt + ((size_t)(b * (NH*NL) + h * NL + lrow)) * SEQ;
    const int kvr = t >> 4;            // 0..15
    const int d4  = (t & 15) * 4;

    const int s0c = chunk * CHUNK;
    for (int stage = 0; stage < CHUNK / 32; stage++) {
        const int sbase = s0c + stage * 32;
        __syncthreads();
        float4 hv = *(const float4*)(dtrow + sbase + s4);
        *(float4*)&sh_hs[lrow][s4] = hv;
        #pragma unroll
        for (int i = 0; i < 2; i++) {
            int si = kvr + i * 16;
            size_t src = ((size_t)(b * SEQ + sbase + si)) * DIMN + h * DH + d4;
            *(float4*)&sh_K[si][d4] = *(const float4*)(K + src);
            *(float4*)&sh_V[si][d4] = *(const float4*)(V + src);
        }
        __syncthreads();
        #pragma unroll 4
        for (int si = 0; si < 32; si++) {
            float kv = sh_K[si][d], vv = sh_V[si][d];
            #pragma unroll
            for (int li = 0; li < 8; li++) {
                float hsv = sh_hs[lbase + li][si];
                accK[li] = fmaf(hsv, kv, accK[li]);
                accV[li] = fmaf(hsv, vv, accV[li]);
            }
        }
    }
    #pragma unroll
    for (int li = 0; li < 8; li++) {
        size_t idx = (((size_t)bh * NCH + chunk) * NL + lbase + li) * DH + d;
        partK[idx] = accK[li];
        partV[idx] = accV[li];
    }
}

// ---------------- reduce partials -> Kc/Vc laid out (b, l, h*64+d) ----------------
__global__ void __launch_bounds__(256)
reduce_kc(const float* __restrict__ partK, const float* __restrict__ partV,
          float* __restrict__ Kc, float* __restrict__ Vc)
{
    const int e = blockIdx.x * 256 + threadIdx.x;
    const int d = e & 63;
    const int h = (e >> 6) & 15;
    const int l = (e >> 10) & 31;
    const int b = e >> 15;
    const int bh = b * NH + h;
    float sK = 0.f, sV = 0.f;
    #pragma unroll
    for (int c = 0; c < NCH; c++) {
        size_t idx = (((size_t)bh * NCH + c) * NL + l) * DH + d;
        sK += partK[idx];
        sV += partV[idx];
    }
    size_t o = ((size_t)(b * NL + l)) * DIMN + h * DH + d;
    Kc[o] = sK;
    Vc[o] = sV;
}

// ---------------- fused attention (compressed 32 keys + window 16 keys) ----------------
#define GPB 2
#define NQ  (GPB*WW)               // 16 queries per block
#define NWK ((GPB-1)*WW + BAND)    // 24 window rows

__global__ void __launch_bounds__(256)
attn_kernel(const float* __restrict__ Q, const float* __restrict__ K,
            const float* __restrict__ V, const float* __restrict__ Kc,
            const float* __restrict__ Vc, float* __restrict__ C)
{
    const int gblk = blockIdx.x;
    const int h = blockIdx.y;
    const int b = blockIdx.z;
    const int s0  = gblk * NQ;
    const int wk0 = s0 - EE;

    __shared__ float sKc[NL][68];
    __shared__ float sVc[NL][68];
    __shared__ float sKw[NWK][68];
    __shared__ float sVw[NWK][68];
    __shared__ float sQ [NQ][68];
    __shared__ float sp [NQ][48];

    const int t = threadIdx.x;

    for (int i = t; i < NL * DH; i += 256) {
        int l = i >> 6, d = i & 63;
        size_t src = ((size_t)(b * NL + l)) * DIMN + h * DH + d;
        sKc[l][d] = Kc[src];
        sVc[l][d] = Vc[src];
    }
    for (int i = t; i < NQ * DH; i += 256) {
        int q = i >> 6, d = i & 63;
        sQ[q][d] = Q[((size_t)(b * SEQ + s0 + q)) * DIMN + h * DH + d];
    }
    for (int i = t; i < NWK * DH; i += 256) {
        int r = i >> 6, d = i & 63;
        int sk = wk0 + r;
        float kv = 0.f, vv = 0.f;
        if (sk >= 0 && sk < SEQ) {
            size_t src = ((size_t)(b * SEQ + sk)) * DIMN + h * DH + d;
            kv = K[src]; vv = V[src];
        }
        sKw[r][d] = kv;
        sVw[r][d] = vv;
    }
    __syncthreads();

    const int warp = t >> 5, lane = t & 31;
    #pragma unroll
    for (int qq = 0; qq < 2; qq++) {
        const int q = warp * 2 + qq;
        const int grp = q >> 3;
        const int woff = grp * WW;
        const float* qrow  = sQ[q];
        const float* krow0 = sKc[lane];
        const float* krow1 = sKw[woff + (lane & 15)];
        float sc0 = 0.f, sc1 = 0.f;
        #pragma unroll
        for (int dd = 0; dd < DH; dd += 4) {
            float4 qa = *(const float4*)(qrow + dd);
            float4 ka = *(const float4*)(krow0 + dd);
            float4 kb = *(const float4*)(krow1 + dd);
            sc0 += qa.x*ka.x + qa.y*ka.y + qa.z*ka.z + qa.w*ka.w;
            sc1 += qa.x*kb.x + qa.y*kb.y + qa.z*kb.z + qa.w*kb.w;
        }
        bool wvalid = (lane < 16);
        if (wvalid) {
            int sk = wk0 + woff + lane;
            if (sk < 0 || sk >= SEQ) wvalid = false;
        }
        float swin = wvalid ? sc1 : -1e30f;
        float m = fmaxf(sc0, swin);
        #pragma unroll
        for (int o = 16; o; o >>= 1) m = fmaxf(m, __shfl_xor_sync(0xffffffffu, m, o));
        float e0 = expf(sc0 - m);
        float e1 = wvalid ? expf(swin - m) : 0.f;
        float ssum = e0 + e1;
        #pragma unroll
        for (int o = 16; o; o >>= 1) ssum += __shfl_xor_sync(0xffffffffu, ssum, o);
        float inv = 1.f / ssum;
        sp[q][lane] = e0 * inv;
        if (lane < 16) sp[q][32 + lane] = e1 * inv;
    }
    __syncthreads();

    for (int i = t; i < NQ * DH; i += 256) {
        int q = i >> 6, d = i & 63;
        int woff = (q >> 3) * WW;
        float acc = 0.f;
        #pragma unroll
        for (int l = 0; l < NL; l++) acc = fmaf(sp[q][l], sVc[l][d], acc);
        #pragma unroll
        for (int j = 0; j < BAND; j++) acc = fmaf(sp[q][32 + j], sVw[woff + j][d], acc);
        C[((size_t)(b * SEQ + s0 + q)) * DIMN + h * DH + d] = acc;
    }
}

// ---------------- launch ----------------
extern "C" void kernel_launch(void* const* d_in, const int* in_sizes, int n_in,
                              void* d_out, int out_size)
{
    const float* query = (const float*)d_in[0];
    const float* Wq  = (const float*)d_in[1];
    const float* bq  = (const float*)d_in[2];
    const float* Wk  = (const float*)d_in[3];
    const float* bk  = (const float*)d_in[4];
    const float* Wv  = (const float*)d_in[5];
    const float* bv  = (const float*)d_in[6];
    const float* Wo  = (const float*)d_in[7];
    const float* bo  = (const float*)d_in[8];
    const float* g_l = (const float*)d_in[9];
    const float* b_l = (const float*)d_in[10];
    const float* g_s = (const float*)d_in[11];
    const float* b_s = (const float*)d_in[12];
    const float* Wd  = (const float*)d_in[13];
    const float* bd  = (const float*)d_in[14];
    float* out = (float*)d_out;

    float *Qb, *Kb, *Vb, *Db, *Cb, *Kcb, *Vcb, *pK, *pV;
    cudaGetSymbolAddress((void**)&Qb,  g_Q);
    cudaGetSymbolAddress((void**)&Kb,  g_K);
    cudaGetSymbolAddress((void**)&Vb,  g_V);
    cudaGetSymbolAddress((void**)&Db,  g_Ds);
    cudaGetSymbolAddress((void**)&Cb,  g_C);
    cudaGetSymbolAddress((void**)&Kcb, g_Kc);
    cudaGetSymbolAddress((void**)&Vcb, g_Vc);
    cudaGetSymbolAddress((void**)&pK,  g_pK);
    cudaGetSymbolAddress((void**)&pV,  g_pV);

    static int smem_set = 0;
    if (!smem_set) {
        cudaFuncSetAttribute(gemm_tf32, cudaFuncAttributeMaxDynamicSharedMemorySize, GEMM_SMEM);
        smem_set = 1;
    }

    // Projections (tf32 tensor cores)
    gemm_tf32<<<dim3(8, 128), 256, GEMM_SMEM>>>(query, Wq, bq, Qb, 1024, 0.125f, 1, 0);
    gemm_tf32<<<dim3(8, 128), 256, GEMM_SMEM>>>(query, Wk, bk, Kb, 1024, 1.0f,   1, 0);
    gemm_tf32<<<dim3(8, 128), 256, GEMM_SMEM>>>(query, Wv, bv, Vb, 1024, 1.0f,   1, 0);
    gemm_tf32<<<dim3(4, 128), 256, GEMM_SMEM>>>(query, Wd, bd, Db,  512, 1.0f,   1, 2);

    // LayerNorm on K, V
    ln_kernel<<<MROWS, 256>>>(Kb, g_l, b_l);
    ln_kernel<<<MROWS, 256>>>(Vb, g_l, b_l);

    // head_scores softmax over sequence axis (contiguous rows of Dt)
    dsoftmax_kernel<<<BATCH * NH * NL, 256>>>(Db);

    // Compression
    compress_kernel<<<dim3(BATCH * NH, NCH), 256>>>(Db, Kb, Vb, pK, pV);
    reduce_kc<<<(BATCH * NL * DIMN) / 256, 256>>>(pK, pV, Kcb, Vcb);

    // LayerNorm on compressed K/V
    ln_kernel<<<BATCH * NL, 256>>>(Kcb, g_s, b_s);
    ln_kernel<<<BATCH * NL, 256>>>(Vcb, g_s, b_s);

    // Fused long-short attention
    attn_kernel<<<dim3(SEQ / NQ, NH, BATCH), 256>>>(Qb, Kb, Vb, Kcb, Vcb, Cb);

    // Output projection with transposed write to (s, b, DIM)
    gemm_tf32<<<dim3(8, 128), 256, GEMM_SMEM>>>(Cb, Wo, bo, out, 1024, 1.0f, 0, 1);
}